// round 2
// baseline (speedup 1.0000x reference)
#include <cuda_runtime.h>

#define L   8192
#define CH  512
#define N   64
#define NC  64
#define T   128   // L / NC

// ---- scratch / constants (no allocation allowed) ----
__device__ float d_Abar[N];
__device__ float d_CB[N];
__device__ float d_AbarT[N];
__device__ float d_S[(size_t)NC * CH * N];   // per-chunk local end states (g-space)
__device__ float d_H[(size_t)NC * CH * N];   // carry-in state per chunk (g-space)

// ---- packed f32x2 helpers ----
__device__ __forceinline__ unsigned long long pack2(float lo, float hi) {
    unsigned long long r;
    asm("mov.b64 %0, {%1, %2};" : "=l"(r) : "f"(lo), "f"(hi));
    return r;
}
__device__ __forceinline__ void unpack2(unsigned long long v, float& lo, float& hi) {
    asm("mov.b64 {%0, %1}, %2;" : "=f"(lo), "=f"(hi) : "l"(v));
}
__device__ __forceinline__ unsigned long long fma2(unsigned long long a,
                                                   unsigned long long b,
                                                   unsigned long long c) {
    unsigned long long r;
    asm("fma.rn.f32x2 %0, %1, %2, %3;" : "=l"(r) : "l"(a), "l"(b), "l"(c));
    return r;
}

// ---- pass 0: derive discretized coefficients ----
__global__ void precompute_kernel(const float* __restrict__ logA,
                                  const float* __restrict__ B,
                                  const float* __restrict__ C) {
    int n = threadIdx.x;
    if (n >= N) return;
    const float dt = 1.0f / 4096.0f;
    float A    = -expf(logA[n]);
    float Abar = expf(A * dt);
    float Bbar = (Abar - 1.0f) * B[n] / A;
    d_Abar[n]  = Abar;
    d_CB[n]    = C[n] * Bbar;
    d_AbarT[n] = expf(A * dt * (float)T);   // Abar^T
}

// ---- pass 1: local chunk scan (zero init), store end state S only ----
__global__ void __launch_bounds__(128) scan_local_kernel(const float* __restrict__ x) {
    __shared__ float xs[T][64];
    const int j   = blockIdx.x;        // chunk
    const int cg  = blockIdx.y;        // channel group (64 channels)
    const int tid = threadIdx.x;

    // stage x tile [T x 64] (coalesced float4)
    for (int i = tid; i < T * 16; i += 128) {
        int r = i >> 4, q = i & 15;
        float4 v = *(const float4*)(x + (size_t)(j * T + r) * CH + cg * 64 + q * 4);
        *(float4*)&xs[r][q * 4] = v;
    }
    __syncthreads();

    const int chl  = tid >> 1;         // local channel 0..63
    const int half = tid & 1;          // which 32 states

    unsigned long long a2[16], g2[16];
    const float2* Ab = (const float2*)d_Abar;
#pragma unroll
    for (int k = 0; k < 16; k++) {
        float2 a = Ab[half * 16 + k];
        a2[k] = pack2(a.x, a.y);
        g2[k] = 0ULL;                  // {0.f, 0.f}
    }

#pragma unroll 4
    for (int t = 0; t < T; t++) {
        float xv = xs[t][chl];
        unsigned long long x2 = pack2(xv, xv);
#pragma unroll
        for (int k = 0; k < 16; k++) g2[k] = fma2(a2[k], g2[k], x2);
    }

    unsigned long long* Sp = (unsigned long long*)
        (d_S + (((size_t)j * CH) + (size_t)cg * 64 + chl) * N + half * 32);
#pragma unroll
    for (int k = 0; k < 16; k++) Sp[k] = g2[k];
}

// ---- pass 2: sequential prefix over chunks (tiny) ----
__global__ void carry_kernel() {
    int idx = blockIdx.x * blockDim.x + threadIdx.x;   // 0 .. CH*N/4-1 = 8191
    if (idx >= CH * N / 4) return;
    int c  = idx >> 4;
    int n4 = (idx & 15) * 4;
    float4 aT = *(const float4*)(d_AbarT + n4);
    float4 carry = make_float4(0.f, 0.f, 0.f, 0.f);
    for (int j = 0; j < NC; j++) {
        size_t off = (((size_t)j * CH) + c) * N + n4;
        *(float4*)(d_H + off) = carry;                 // carry INTO chunk j
        float4 s = *(const float4*)(d_S + off);
        carry.x = fmaf(aT.x, carry.x, s.x);
        carry.y = fmaf(aT.y, carry.y, s.y);
        carry.z = fmaf(aT.z, carry.z, s.z);
        carry.w = fmaf(aT.w, carry.w, s.w);
    }
}

// ---- pass 3: replay chunk with exact carry, emit y ----
__global__ void __launch_bounds__(128) scan_final_kernel(const float* __restrict__ x,
                                                         float* __restrict__ y) {
    __shared__ float xs[T][64];
    const int j   = blockIdx.x;
    const int cg  = blockIdx.y;
    const int tid = threadIdx.x;

    for (int i = tid; i < T * 16; i += 128) {
        int r = i >> 4, q = i & 15;
        float4 v = *(const float4*)(x + (size_t)(j * T + r) * CH + cg * 64 + q * 4);
        *(float4*)&xs[r][q * 4] = v;
    }
    __syncthreads();

    const int chl  = tid >> 1;
    const int half = tid & 1;
    const int c    = cg * 64 + chl;

    unsigned long long a2[16], cb2[16], g2[16];
    const float2* Ab = (const float2*)d_Abar;
    const float2* Cb = (const float2*)d_CB;
    const unsigned long long* Hp = (const unsigned long long*)
        (d_H + (((size_t)j * CH) + c) * N + half * 32);
#pragma unroll
    for (int k = 0; k < 16; k++) {
        float2 a = Ab[half * 16 + k];
        float2 cb = Cb[half * 16 + k];
        a2[k]  = pack2(a.x, a.y);
        cb2[k] = pack2(cb.x, cb.y);
        g2[k]  = Hp[k];
    }

#pragma unroll 2
    for (int t = 0; t < T; t++) {
        float xv = xs[t][chl];
        unsigned long long x2 = pack2(xv, xv);
#pragma unroll
        for (int k = 0; k < 16; k++) g2[k] = fma2(a2[k], g2[k], x2);

        unsigned long long acc0 = 0ULL, acc1 = 0ULL;
#pragma unroll
        for (int k = 0; k < 16; k += 2) {
            acc0 = fma2(cb2[k],     g2[k],     acc0);
            acc1 = fma2(cb2[k + 1], g2[k + 1], acc1);
        }
        float l0, h0, l1, h1;
        unpack2(acc0, l0, h0);
        unpack2(acc1, l1, h1);
        float yp = (l0 + h0) + (l1 + h1);
        float ys = yp + __shfl_xor_sync(0xffffffffu, yp, 1);
        if (half == 0) y[(size_t)(j * T + t) * CH + c] = ys;
    }
}

extern "C" void kernel_launch(void* const* d_in, const int* in_sizes, int n_in,
                              void* d_out, int out_size) {
    const float* x    = (const float*)d_in[0];
    const float* logA = (const float*)d_in[1];
    const float* B    = (const float*)d_in[2];
    const float* C    = (const float*)d_in[3];
    float* y = (float*)d_out;

    precompute_kernel<<<1, 64>>>(logA, B, C);
    scan_local_kernel<<<dim3(NC, CH / 64), 128>>>(x);
    carry_kernel<<<(CH * N / 4 + 127) / 128, 128>>>();
    scan_final_kernel<<<dim3(NC, CH / 64), 128>>>(x, y);
}

// round 3
// speedup vs baseline: 1.2724x; 1.2724x over previous
#include <cuda_runtime.h>

#define L   8192
#define CH  512
#define N   64
#define NC  64
#define T   128   // L / NC
#define CPB 32    // channels per block
#define TPC 4     // threads per channel
#define NPT 16    // states per thread (N / TPC)

// ---- scratch / constants (no allocation allowed) ----
__device__ float d_Abar[N];
__device__ float d_CB[N];
__device__ float d_AbarT[N];
__device__ float d_S[(size_t)NC * CH * N];   // per-chunk local end states (g-space)
__device__ float d_H[(size_t)NC * CH * N];   // carry-in state per chunk (g-space)

// ---- packed f32x2 helpers ----
__device__ __forceinline__ unsigned long long pack2(float lo, float hi) {
    unsigned long long r;
    asm("mov.b64 %0, {%1, %2};" : "=l"(r) : "f"(lo), "f"(hi));
    return r;
}
__device__ __forceinline__ void unpack2(unsigned long long v, float& lo, float& hi) {
    asm("mov.b64 {%0, %1}, %2;" : "=f"(lo), "=f"(hi) : "l"(v));
}
__device__ __forceinline__ unsigned long long fma2(unsigned long long a,
                                                   unsigned long long b,
                                                   unsigned long long c) {
    unsigned long long r;
    asm("fma.rn.f32x2 %0, %1, %2, %3;" : "=l"(r) : "l"(a), "l"(b), "l"(c));
    return r;
}

// ---- pass 0: derive discretized coefficients ----
__global__ void precompute_kernel(const float* __restrict__ logA,
                                  const float* __restrict__ B,
                                  const float* __restrict__ C) {
    int n = threadIdx.x;
    if (n >= N) return;
    const float dt = 1.0f / 4096.0f;
    float A    = -expf(logA[n]);
    float Abar = expf(A * dt);
    float Bbar = (Abar - 1.0f) * B[n] / A;
    d_Abar[n]  = Abar;
    d_CB[n]    = C[n] * Bbar;
    d_AbarT[n] = expf(A * dt * (float)T);   // Abar^T
}

// ---- pass 1: local chunk scan (zero init), store end state S only ----
// block: 128 threads = 32 channels x 4 threads; each thread owns 16 states.
__global__ void __launch_bounds__(128, 6) scan_local_kernel(const float* __restrict__ x) {
    __shared__ float xs[T][CPB];
    const int j   = blockIdx.x;        // chunk
    const int cg  = blockIdx.y;        // channel group (32 channels)
    const int tid = threadIdx.x;

    // stage x tile [T x 32] (coalesced float4): T*8 float4s over 128 threads
    for (int i = tid; i < T * (CPB / 4); i += 128) {
        int r = i >> 3, q = i & 7;
        float4 v = *(const float4*)(x + (size_t)(j * T + r) * CH + cg * CPB + q * 4);
        *(float4*)&xs[r][q * 4] = v;
    }
    __syncthreads();

    const int chl = tid >> 2;          // local channel 0..31
    const int qs  = tid & 3;           // which 16 states

    unsigned long long a2[NPT / 2], g2[NPT / 2];
    const float2* Ab = (const float2*)d_Abar;
#pragma unroll
    for (int k = 0; k < NPT / 2; k++) {
        float2 a = Ab[qs * (NPT / 2) + k];
        a2[k] = pack2(a.x, a.y);
        g2[k] = 0ULL;
    }

#pragma unroll 8
    for (int t = 0; t < T; t++) {
        float xv = xs[t][chl];
        unsigned long long x2 = pack2(xv, xv);
#pragma unroll
        for (int k = 0; k < NPT / 2; k++) g2[k] = fma2(a2[k], g2[k], x2);
    }

    unsigned long long* Sp = (unsigned long long*)
        (d_S + (((size_t)j * CH) + (size_t)cg * CPB + chl) * N + qs * NPT);
#pragma unroll
    for (int k = 0; k < NPT / 2; k++) Sp[k] = g2[k];
}

// ---- pass 2: sequential prefix over chunks (tiny) ----
__global__ void carry_kernel() {
    int idx = blockIdx.x * blockDim.x + threadIdx.x;   // 0 .. CH*N/4-1 = 8191
    if (idx >= CH * N / 4) return;
    int c  = idx >> 4;
    int n4 = (idx & 15) * 4;
    float4 aT = *(const float4*)(d_AbarT + n4);
    float4 carry = make_float4(0.f, 0.f, 0.f, 0.f);
#pragma unroll 4
    for (int j = 0; j < NC; j++) {
        size_t off = (((size_t)j * CH) + c) * N + n4;
        float4 s = *(const float4*)(d_S + off);           // independent load, pipelines
        *(float4*)(d_H + off) = carry;                    // carry INTO chunk j
        carry.x = fmaf(aT.x, carry.x, s.x);
        carry.y = fmaf(aT.y, carry.y, s.y);
        carry.z = fmaf(aT.z, carry.z, s.z);
        carry.w = fmaf(aT.w, carry.w, s.w);
    }
}

// ---- pass 3: replay chunk with exact carry, emit y ----
__global__ void __launch_bounds__(128, 6) scan_final_kernel(const float* __restrict__ x,
                                                            float* __restrict__ y) {
    __shared__ float xs[T][CPB];
    const int j   = blockIdx.x;
    const int cg  = blockIdx.y;
    const int tid = threadIdx.x;

    for (int i = tid; i < T * (CPB / 4); i += 128) {
        int r = i >> 3, q = i & 7;
        float4 v = *(const float4*)(x + (size_t)(j * T + r) * CH + cg * CPB + q * 4);
        *(float4*)&xs[r][q * 4] = v;
    }
    __syncthreads();

    const int chl = tid >> 2;
    const int qs  = tid & 3;
    const int c   = cg * CPB + chl;

    unsigned long long a2[NPT / 2], cb2[NPT / 2], g2[NPT / 2];
    const float2* Ab = (const float2*)d_Abar;
    const float2* Cb = (const float2*)d_CB;
    const unsigned long long* Hp = (const unsigned long long*)
        (d_H + (((size_t)j * CH) + c) * N + qs * NPT);
#pragma unroll
    for (int k = 0; k < NPT / 2; k++) {
        float2 a  = Ab[qs * (NPT / 2) + k];
        float2 cb = Cb[qs * (NPT / 2) + k];
        a2[k]  = pack2(a.x, a.y);
        cb2[k] = pack2(cb.x, cb.y);
        g2[k]  = Hp[k];
    }

    float* yrow = y + c;
#pragma unroll 4
    for (int t = 0; t < T; t++) {
        float xv = xs[t][chl];
        unsigned long long x2 = pack2(xv, xv);
#pragma unroll
        for (int k = 0; k < NPT / 2; k++) g2[k] = fma2(a2[k], g2[k], x2);

        // dot: two independent chains of 4
        unsigned long long acc0 = 0ULL, acc1 = 0ULL;
#pragma unroll
        for (int k = 0; k < NPT / 2; k += 2) {
            acc0 = fma2(cb2[k],     g2[k],     acc0);
            acc1 = fma2(cb2[k + 1], g2[k + 1], acc1);
        }
        float l0, h0, l1, h1;
        unpack2(acc0, l0, h0);
        unpack2(acc1, l1, h1);
        float yp = (l0 + h0) + (l1 + h1);
        yp += __shfl_xor_sync(0xffffffffu, yp, 1);
        yp += __shfl_xor_sync(0xffffffffu, yp, 2);
        if (qs == 0) yrow[(size_t)(j * T + t) * CH] = yp;
    }
}

extern "C" void kernel_launch(void* const* d_in, const int* in_sizes, int n_in,
                              void* d_out, int out_size) {
    const float* x    = (const float*)d_in[0];
    const float* logA = (const float*)d_in[1];
    const float* B    = (const float*)d_in[2];
    const float* C    = (const float*)d_in[3];
    float* y = (float*)d_out;

    precompute_kernel<<<1, 64>>>(logA, B, C);
    scan_local_kernel<<<dim3(NC, CH / CPB), 128>>>(x);
    carry_kernel<<<(CH * N / 4 + 127) / 128, 128>>>();
    scan_final_kernel<<<dim3(NC, CH / CPB), 128>>>(x, y);
}